// round 15
// baseline (speedup 1.0000x reference)
#include <cuda_runtime.h>
#include <cuda_fp16.h>
#include <cstdint>

// ---------------------------------------------------------------------------
// SNNEmbeddingModel: B=8, S=128, D=512, N_in=N_out=1024, T=32, alpha=0.9
//
//   k0 : W_conn -> fp16 {hi, lo*2^11} planes, transposed to [n][k]
//   k0c: W_out  -> fp16 {hi, lo*2^11} planes, transposed to [d][k]
//   k1 : snn_input = relu(emb @ W_in + b_in)  fp32 SIMT (input path: exact)
//   k2 : input LIF scan, 2 neurons/thread, x(s+1) prefetched; launched as
//        16 CTAs x 256 thr so 2 warps/SMSP interleave the scan chains
//   k3 : I = s_in @ W^T  HMMA, cp.async 3-stage pipeline, 2 passes
//   k4 : output LIF scan over 6-deep cp.async smem ring (64 thr, 1 col)
//   k5h: out = spike_acc @ W_out + b_out  HMMA, 2 passes (+ spike_rate)
// ---------------------------------------------------------------------------

namespace {
constexpr float kAlpha  = 0.9f;
constexpr float kThresh = 1.0f;
constexpr int kB = 8, kS = 128, kD = 512, kNin = 1024, kNout = 1024, kT = 32;
constexpr int kM = kS * kT * kB;          // 32768 rows, m = u*8 + b
constexpr int BM = 128, BN = 128, BK = 64, STAGES = 3;
constexpr int kStageBytes = (BM * BK + BN * BK) * 2;     // 32 KB
constexpr int kSmemGemm = STAGES * kStageBytes;          // 96 KB
constexpr int kKIters = 2 * (kNin / BK);                 // 32 (lo pass + hi pass)
constexpr int kRing = 6;                                 // k4 ring depth (48 KB)
}  // namespace

// Scratch (device globals; no allocation allowed).
__device__ float g_snn[(size_t)kB * kS * kNin];                   //   4 MB
__device__ __align__(16) __half g_sin[(size_t)kM * kNin];         //  64 MB
__device__ __align__(16) __half g_Wt[2][(size_t)kNout * kNin];    //   4 MB
__device__ __align__(16) __half g_Wout[2][(size_t)kD * kNout];    //   2 MB
__device__ float g_cur[(size_t)kM * kNout];                       // 128 MB
__device__ __align__(16) __half g_sacch[(size_t)kS * kB * kNout]; //   2 MB
__device__ unsigned long long g_spk;

// ------------------------------- helpers ----------------------------------
__device__ __forceinline__ uint32_t smem_u32(const void* p) {
  uint32_t a;
  asm("{ .reg .u64 t; cvta.to.shared.u64 t, %1; cvt.u32.u64 %0, t; }"
      : "=r"(a) : "l"(p));
  return a;
}
__device__ __forceinline__ uint32_t swz128(uint32_t off) {
  return off ^ ((off >> 3) & 0x70);   // 16B-chunk xor within 128B rows
}
__device__ __forceinline__ void cp_async16(uint32_t dst, const void* src) {
  asm volatile("cp.async.cg.shared.global [%0], [%1], 16;"
               :: "r"(dst), "l"(src) : "memory");
}
__device__ __forceinline__ void ldsm_x4(uint32_t* r, uint32_t addr) {
  asm volatile("ldmatrix.sync.aligned.m8n8.x4.shared.b16 {%0,%1,%2,%3}, [%4];"
               : "=r"(r[0]), "=r"(r[1]), "=r"(r[2]), "=r"(r[3]) : "r"(addr));
}
__device__ __forceinline__ void mma16816(float* c, const uint32_t* a,
                                         const uint32_t* b) {
  asm volatile(
      "mma.sync.aligned.m16n8k16.row.col.f32.f16.f16.f32 "
      "{%0,%1,%2,%3}, {%4,%5,%6,%7}, {%8,%9}, {%0,%1,%2,%3};"
      : "+f"(c[0]), "+f"(c[1]), "+f"(c[2]), "+f"(c[3])
      : "r"(a[0]), "r"(a[1]), "r"(a[2]), "r"(a[3]), "r"(b[0]), "r"(b[1]));
}
__device__ __forceinline__ void split16(float w, __half& hi, __half& lo) {
  hi = __float2half_rn(w);
  lo = __float2half_rn((w - __half2float(hi)) * 2048.0f);
}

// ---------------------------------------------------------------------------
// k0: transpose + split W_conn [k][n] -> g_Wt[{hi,lo}][n][k]. Zeroes g_spk.
// ---------------------------------------------------------------------------
__global__ void k0_prep(const float* __restrict__ W) {
  __shared__ float t[32][33];
  const int tx = threadIdx.x, ty = threadIdx.y;  // (32, 8)
  const int n0 = blockIdx.x * 32, k0 = blockIdx.y * 32;
  if (blockIdx.x == 0 && blockIdx.y == 0 && tx == 0 && ty == 0) g_spk = 0ull;
#pragma unroll
  for (int i = ty; i < 32; i += 8)
    t[i][tx] = W[(size_t)(k0 + i) * kNout + n0 + tx];
  __syncthreads();
#pragma unroll
  for (int i = ty; i < 32; i += 8) {
    const int n = n0 + i, k = k0 + tx;
    __half hi, lo;
    split16(t[tx][i], hi, lo);
    const size_t off = (size_t)n * kNin + k;
    g_Wt[0][off] = hi; g_Wt[1][off] = lo;
  }
}

// k0c: transpose + split W_out [1024][512] -> g_Wout[.][d][k], k<1024.
__global__ void k0c_wout(const float* __restrict__ W) {
  __shared__ float t[32][33];
  const int tx = threadIdx.x, ty = threadIdx.y;
  const int d0 = blockIdx.x * 32, k0 = blockIdx.y * 32;
#pragma unroll
  for (int i = ty; i < 32; i += 8)
    t[i][tx] = W[(size_t)(k0 + i) * kD + d0 + tx];
  __syncthreads();
#pragma unroll
  for (int i = ty; i < 32; i += 8) {
    const int d = d0 + i, k = k0 + tx;
    __half hi, lo;
    split16(t[tx][i], hi, lo);
    const size_t off = (size_t)d * kNout + k;
    g_Wout[0][off] = hi; g_Wout[1][off] = lo;
  }
}

// ---------------------------------------------------------------------------
// k1: 64x64x16 tiled fp32 GEMM, C = relu(emb @ W_in + b_in). [1024x1024] K=512.
// (proven — input-population path must stay fp32-exact)
// ---------------------------------------------------------------------------
__global__ void k1_gemm_in(const float* __restrict__ A, const float* __restrict__ W,
                           const float* __restrict__ bias) {
  __shared__ float As[16][66];
  __shared__ float Bs[16][64];
  const int tid = threadIdx.x;
  const int bm = blockIdx.y * 64, bn = blockIdx.x * 64;
  const int tr = (tid >> 4) * 4, tc = (tid & 15) * 4;
  const int arow = tid >> 2, ak = (tid & 3) * 4;
  const int brow = tid >> 4, bcol = (tid & 15) * 4;

  float acc[4][4] = {};
  for (int kk = 0; kk < kD; kk += 16) {
    float4 av = *reinterpret_cast<const float4*>(&A[(size_t)(bm + arow) * kD + kk + ak]);
    float4 bv = *reinterpret_cast<const float4*>(&W[(size_t)(kk + brow) * kNin + bn + bcol]);
    As[ak + 0][arow] = av.x; As[ak + 1][arow] = av.y;
    As[ak + 2][arow] = av.z; As[ak + 3][arow] = av.w;
    *reinterpret_cast<float4*>(&Bs[brow][bcol]) = bv;
    __syncthreads();
#pragma unroll
    for (int k = 0; k < 16; k++) {
      float a[4], b[4];
#pragma unroll
      for (int i = 0; i < 4; i++) a[i] = As[k][tr + i];
#pragma unroll
      for (int j = 0; j < 4; j++) b[j] = Bs[k][tc + j];
#pragma unroll
      for (int i = 0; i < 4; i++)
#pragma unroll
        for (int j = 0; j < 4; j++) acc[i][j] = fmaf(a[i], b[j], acc[i][j]);
    }
    __syncthreads();
  }
#pragma unroll
  for (int i = 0; i < 4; i++)
#pragma unroll
    for (int j = 0; j < 4; j++) {
      const int n = bn + tc + j;
      g_snn[(size_t)(bm + tr + i) * kNin + n] = fmaxf(acc[i][j] + bias[n], 0.0f);
    }
}

// ---------------------------------------------------------------------------
// k2: input LIF. Thread per (b, n-pair): dual FFMA->FSETP->FSEL chains;
// x(s+1) register-prefetched. Launched 16 CTAs x 256 threads so each SMSP
// holds 2 warps and the scan chains interleave in the issue slots.
// ---------------------------------------------------------------------------
__global__ void __launch_bounds__(256) k2_vin() {
  const int id = blockIdx.x * blockDim.x + threadIdx.x;  // 4096
  const int b = id >> 9;
  const int n = (id & 511) * 2;
  const float2* xsrc =
      reinterpret_cast<const float2*>(&g_snn[(size_t)(b * kS) * kNin + n]);
  const int xstride = kNin / 2;                          // float2 units per s
  float v0 = 0.0f, v1 = 0.0f;
  float total = 0.0f;
  float2 x = xsrc[0];
  for (int s = 0; s < kS; s++) {
    float2 xn = (s + 1 < kS) ? xsrc[(size_t)(s + 1) * xstride]
                             : make_float2(0.0f, 0.0f);
    const int u0 = s * kT;
#pragma unroll
    for (int t = 0; t < kT; t++) {
      const float vn0 = fmaf(kAlpha, v0, x.x);
      const float vn1 = fmaf(kAlpha, v1, x.y);
      const float vr0 = (vn0 >= kThresh) ? vn0 - kThresh : vn0;
      const float vr1 = (vn1 >= kThresh) ? vn1 - kThresh : vn1;
      const float sp0 = vn0 - vr0;
      const float sp1 = vn1 - vr1;
      total += sp0 + sp1;
      *reinterpret_cast<__half2*>(
          &g_sin[((size_t)(u0 + t) * kB + b) * kNin + n]) =
          __floats2half2_rn(sp0, sp1);
      v0 = vr0; v1 = vr1;
    }
    x = xn;
  }
  atomicAdd(&g_spk, (unsigned long long)(unsigned)total);
}

// ---------------------------------------------------------------------------
// k3: pipelined HMMA GEMM. C[32768 x 1024] = s_in @ (hi + 2^-11 lo)^T.
// (unchanged — measured 317 us, tensor 71%)
// ---------------------------------------------------------------------------
__global__ void __launch_bounds__(256, 2) k3_gemm() {
  extern __shared__ char smem[];
  const uint32_t sbase = smem_u32(smem);
  const int tid = threadIdx.x, wid = tid >> 5, lane = tid & 31;
  const int wm = wid >> 2, wn = wid & 3;
  const int m0 = blockIdx.y * BM, n0 = blockIdx.x * BN;

  auto issue_stage = [&](int kv) {
    if (kv < kKIters) {
      const int stage = kv % STAGES;
      const uint32_t as = sbase + stage * kStageBytes;
      const uint32_t bs = as + BM * BK * 2;
      const int plane = kv >> 4;
      const size_t kt = (size_t)(kv & 15) * BK;
      const char* Ag = (const char*)g_sin + ((size_t)m0 * kNin + kt) * 2;
      const char* Bg = (const char*)(plane ? g_Wt[0] : g_Wt[1]) +
                       ((size_t)n0 * kNin + kt) * 2;
#pragma unroll
      for (int i = 0; i < 4; i++) {
        const int cid = tid + i * 256;
        const int r = cid >> 3, c = cid & 7;
        cp_async16(as + swz128((uint32_t)r * 128 + c * 16),
                   Ag + (size_t)r * (kNin * 2) + c * 16);
      }
#pragma unroll
      for (int i = 0; i < 4; i++) {
        const int cid = tid + i * 256;
        const int r = cid >> 3, c = cid & 7;
        cp_async16(bs + swz128((uint32_t)r * 128 + c * 16),
                   Bg + (size_t)r * (kNin * 2) + c * 16);
      }
    }
    asm volatile("cp.async.commit_group;" ::: "memory");
  };

  issue_stage(0);
  issue_stage(1);

  float acc[4][4][4] = {};
  const int a_row = wm * 64 + (lane & 15);
  const int a_half = lane >> 4;
  const int b_row0 = wn * 32 + ((lane >> 4) * 8) + (lane & 7);
  const int b_half = (lane >> 3) & 1;

  for (int kv = 0; kv < kKIters; kv++) {
    asm volatile("cp.async.wait_group 1;" ::: "memory");
    __syncthreads();
    if (kv == kKIters / 2) {
#pragma unroll
      for (int i = 0; i < 4; i++)
#pragma unroll
        for (int j = 0; j < 4; j++)
#pragma unroll
          for (int q = 0; q < 4; q++) acc[i][j][q] *= (1.0f / 2048.0f);
    }
    const int stage = kv % STAGES;
    const uint32_t as = sbase + stage * kStageBytes;
    const uint32_t bs = as + BM * BK * 2;
#pragma unroll
    for (int ks = 0; ks < 4; ks++) {
      uint32_t a[4][4], b[4][2];
#pragma unroll
      for (int i = 0; i < 4; i++)
        ldsm_x4(a[i], as + swz128((uint32_t)(a_row + i * 16) * 128 +
                                  (ks * 2 + a_half) * 16));
#pragma unroll
      for (int jj = 0; jj < 2; jj++) {
        uint32_t r[4];
        ldsm_x4(r, bs + swz128((uint32_t)(b_row0 + jj * 16) * 128 +
                               (ks * 2 + b_half) * 16));
        b[2 * jj][0] = r[0]; b[2 * jj][1] = r[1];
        b[2 * jj + 1][0] = r[2]; b[2 * jj + 1][1] = r[3];
      }
#pragma unroll
      for (int i = 0; i < 4; i++)
#pragma unroll
        for (int j = 0; j < 4; j++) mma16816(acc[i][j], a[i], b[j]);
    }
    issue_stage(kv + 2);
  }

  __syncthreads();
  float* E = reinterpret_cast<float*>(smem);
  const int er = lane >> 2, ec = (lane & 3) * 2;
#pragma unroll
  for (int i = 0; i < 4; i++)
#pragma unroll
    for (int j = 0; j < 4; j++) {
      float* e0 = &E[(size_t)(wm * 64 + i * 16 + er) * BN + wn * 32 + j * 8 + ec];
      e0[0] = acc[i][j][0]; e0[1] = acc[i][j][1];
      float* e1 = e0 + 8 * BN;
      e1[0] = acc[i][j][2]; e1[1] = acc[i][j][3];
    }
  __syncthreads();
#pragma unroll
  for (int q = 0; q < 16; q++) {
    const int idx = tid + q * 256;
    const int r = idx >> 5, c4 = (idx & 31) * 4;
    *reinterpret_cast<float4*>(&g_cur[(size_t)(m0 + r) * kNout + n0 + c4]) =
        *reinterpret_cast<const float4*>(&E[(size_t)r * BN + c4]);
  }
}

// ---------------------------------------------------------------------------
// k4: output LIF via cp.async smem ring (slot = position % kRing). 64 threads
// per CTA, 1 j-column each; fp16 spike_acc stores.
// ---------------------------------------------------------------------------
__global__ void __launch_bounds__(64) k4_vout() {
  __shared__ __align__(16) float sbuf[kRing][kT][64];  // 48 KB ring
  const int tid = threadIdx.x;
  const int b = blockIdx.y;
  const int j0 = blockIdx.x * 64;
  const uint32_t sb = smem_u32(sbuf);

#pragma unroll
  for (int s = 0; s < kRing - 1; s++) {
#pragma unroll
    for (int q = 0; q < 8; q++) {
      const int c = tid + q * 64;
      const int t = c >> 4, x = c & 15;
      cp_async16(sb + (uint32_t)(((s * kT + t) * 64) + x * 4) * 4,
                 &g_cur[((size_t)(s * kT + t) * kB + b) * kNout + j0 + x * 4]);
    }
    asm volatile("cp.async.commit_group;" ::: "memory");
  }

  float v = 0.0f;
  float total = 0.0f;
  for (int s = 0; s < kS; s++) {
    asm volatile("cp.async.wait_group %0;" :: "n"(kRing - 2) : "memory");
    __syncthreads();
    const int buf = s % kRing;
    float acc = 0.0f;
#pragma unroll
    for (int t = 0; t < kT; t++) {
      const float vn = fmaf(kAlpha, v, sbuf[buf][t][tid]);
      const float vr = (vn >= kThresh) ? vn - kThresh : vn;
      acc += vn - vr;
      v = vr;
    }
    g_sacch[(size_t)(s * kB + b) * kNout + j0 + tid] = __float2half_rn(acc);
    total += acc;
    __syncthreads();
    const int sn = s + kRing - 1;
    if (sn < kS) {
      const int slot = sn % kRing;
#pragma unroll
      for (int q = 0; q < 8; q++) {
        const int c = tid + q * 64;
        const int t = c >> 4, x = c & 15;
        cp_async16(sb + (uint32_t)(((slot * kT + t) * 64) + x * 4) * 4,
                   &g_cur[((size_t)(sn * kT + t) * kB + b) * kNout + j0 + x * 4]);
      }
    }
    asm volatile("cp.async.commit_group;" ::: "memory");
  }
  atomicAdd(&g_spk, (unsigned long long)(unsigned)total);
}

// ---------------------------------------------------------------------------
// k5h: HMMA GEMM. out = spike_acc @ W_out + b_out, permuted store [b][s][d].
// M=1024 (rows s*8+b), N=512, K=1024; lo pass then hi pass (A is exact fp16).
// ---------------------------------------------------------------------------
__global__ void __launch_bounds__(256, 2) k5h_gemm(const float* __restrict__ bias,
                                                   float* __restrict__ out,
                                                   int write_rate) {
  extern __shared__ char smem[];
  const uint32_t sbase = smem_u32(smem);
  const int tid = threadIdx.x, wid = tid >> 5, lane = tid & 31;
  const int wm = wid >> 2, wn = wid & 3;
  const int m0 = blockIdx.y * BM, n0 = blockIdx.x * BN;
  constexpr int IT = 32;

  auto issue_stage = [&](int kv) {
    if (kv < IT) {
      const int stage = kv % STAGES;
      const uint32_t as = sbase + stage * kStageBytes;
      const uint32_t bs = as + BM * BK * 2;
      const size_t kt = (size_t)(kv & 15) * BK;
      const __half* Bp = (kv < 16) ? g_Wout[1] : g_Wout[0];
      const char* Ag = (const char*)(g_sacch + (size_t)m0 * kNout + kt);
      const char* Bg = (const char*)(Bp + (size_t)n0 * kNout + kt);
#pragma unroll
      for (int i = 0; i < 4; i++) {
        const int cid = tid + i * 256;
        const int r = cid >> 3, c = cid & 7;
        cp_async16(as + swz128((uint32_t)r * 128 + c * 16),
                   Ag + (size_t)r * (kNout * 2) + c * 16);
      }
#pragma unroll
      for (int i = 0; i < 4; i++) {
        const int cid = tid + i * 256;
        const int r = cid >> 3, c = cid & 7;
        cp_async16(bs + swz128((uint32_t)r * 128 + c * 16),
                   Bg + (size_t)r * (kNout * 2) + c * 16);
      }
    }
    asm volatile("cp.async.commit_group;" ::: "memory");
  };

  issue_stage(0);
  issue_stage(1);

  float acc[4][4][4] = {};
  const int a_row = wm * 64 + (lane & 15);
  const int a_half = lane >> 4;
  const int b_row0 = wn * 32 + ((lane >> 4) * 8) + (lane & 7);
  const int b_half = (lane >> 3) & 1;

  for (int kv = 0; kv < IT; kv++) {
    asm volatile("cp.async.wait_group 1;" ::: "memory");
    __syncthreads();
    if (kv == 16) {
#pragma unroll
      for (int i = 0; i < 4; i++)
#pragma unroll
        for (int j = 0; j < 4; j++)
#pragma unroll
          for (int q = 0; q < 4; q++) acc[i][j][q] *= (1.0f / 2048.0f);
    }
    const int stage = kv % STAGES;
    const uint32_t as = sbase + stage * kStageBytes;
    const uint32_t bs = as + BM * BK * 2;
#pragma unroll
    for (int ks = 0; ks < 4; ks++) {
      uint32_t a[4][4], b[4][2];
#pragma unroll
      for (int i = 0; i < 4; i++)
        ldsm_x4(a[i], as + swz128((uint32_t)(a_row + i * 16) * 128 +
                                  (ks * 2 + a_half) * 16));
#pragma unroll
      for (int jj = 0; jj < 2; jj++) {
        uint32_t r[4];
        ldsm_x4(r, bs + swz128((uint32_t)(b_row0 + jj * 16) * 128 +
                               (ks * 2 + b_half) * 16));
        b[2 * jj][0] = r[0]; b[2 * jj][1] = r[1];
        b[2 * jj + 1][0] = r[2]; b[2 * jj + 1][1] = r[3];
      }
#pragma unroll
      for (int i = 0; i < 4; i++)
#pragma unroll
        for (int j = 0; j < 4; j++) mma16816(acc[i][j], a[i], b[j]);
    }
    issue_stage(kv + 2);
  }

  __syncthreads();
  float* E = reinterpret_cast<float*>(smem);
  const int er = lane >> 2, ec = (lane & 3) * 2;
#pragma unroll
  for (int i = 0; i < 4; i++)
#pragma unroll
    for (int j = 0; j < 4; j++) {
      float* e0 = &E[(size_t)(wm * 64 + i * 16 + er) * BN + wn * 32 + j * 8 + ec];
      e0[0] = acc[i][j][0]; e0[1] = acc[i][j][1];
      float* e1 = e0 + 8 * BN;
      e1[0] = acc[i][j][2]; e1[1] = acc[i][j][3];
    }
  __syncthreads();
  if (write_rate && blockIdx.x == 0 && blockIdx.y == 0 && tid == 0) {
    out[(size_t)kB * kS * kD] =
        (float)((double)g_spk / (double)((size_t)kB * kS * (kNin + kNout) * kT));
  }
#pragma unroll
  for (int q = 0; q < 16; q++) {
    const int idx = tid + q * 256;
    const int r = idx >> 5, c4 = (idx & 31) * 4;
    const int m = m0 + r;
    const int s = m >> 3, b = m & 7;       // rows are m = s*B + b
    float4 v = *reinterpret_cast<const float4*>(&E[(size_t)r * BN + c4]);
    const float4 bb = *reinterpret_cast<const float4*>(&bias[n0 + c4]);
    v.x += bb.x; v.y += bb.y; v.z += bb.z; v.w += bb.w;
    *reinterpret_cast<float4*>(&out[((size_t)(b * kS + s)) * kD + n0 + c4]) = v;
  }
}

// ---------------------------------------------------------------------------
extern "C" void kernel_launch(void* const* d_in, const int* in_sizes, int n_in,
                              void* d_out, int out_size) {
  const float* emb    = (const float*)d_in[0];
  const float* W_in   = (const float*)d_in[1];
  const float* b_in   = (const float*)d_in[2];
  const float* W_conn = (const float*)d_in[3];
  const float* W_out  = (const float*)d_in[4];
  const float* b_out  = (const float*)d_in[5];
  float* out = (float*)d_out;
  const int write_rate = (out_size > kB * kS * kD) ? 1 : 0;

  cudaFuncSetAttribute(k3_gemm, cudaFuncAttributeMaxDynamicSharedMemorySize, kSmemGemm);
  cudaFuncSetAttribute(k5h_gemm, cudaFuncAttributeMaxDynamicSharedMemorySize, kSmemGemm);

  k0_prep<<<dim3(kNout / 32, kNin / 32), dim3(32, 8)>>>(W_conn);
  k0c_wout<<<dim3(kD / 32, kNout / 32), dim3(32, 8)>>>(W_out);
  k1_gemm_in<<<dim3(kNin / 64, (kB * kS) / 64), 256>>>(emb, W_in, b_in);
  k2_vin<<<16, 256>>>();
  k3_gemm<<<dim3(kNout / BN, kM / BM), 256, kSmemGemm>>>();
  k4_vout<<<dim3(kNout / 64, kB), 64>>>();
  k5h_gemm<<<dim3(kD / BN, (kS * kB) / BM), 256, kSmemGemm>>>(b_out, out, write_rate);
}

// round 16
// speedup vs baseline: 1.1067x; 1.1067x over previous
#include <cuda_runtime.h>
#include <cuda_fp16.h>
#include <cstdint>

// ---------------------------------------------------------------------------
// SNNEmbeddingModel: B=8, S=128, D=512, N_in=N_out=1024, T=32, alpha=0.9
//
//   k0 : W_conn -> fp16 {hi, lo*2^11} planes, transposed to [n][k]
//   k0c: W_out  -> fp16 {hi, lo*2^11} planes, transposed to [d][k]
//   k1 : snn_input = relu(emb @ W_in + b_in)  fp32 SIMT (input path: exact)
//   k2 : input LIF scan, 2 neurons/thread, x(s+1) prefetched (128x32 — proven)
//   k3 : I = s_in @ W^T  HMMA, 64x64 warp tiles (4 warps, 8 LDSM : 32 HMMA),
//        cp.async 3-stage pipeline, 2 passes — halved L1/ldmatrix traffic
//   k4 : output LIF scan over 6-deep cp.async smem ring (64 thr, 1 col)
//   k5h: out = spike_acc @ W_out + b_out  HMMA, 2 passes (+ spike_rate)
// ---------------------------------------------------------------------------

namespace {
constexpr float kAlpha  = 0.9f;
constexpr float kThresh = 1.0f;
constexpr int kB = 8, kS = 128, kD = 512, kNin = 1024, kNout = 1024, kT = 32;
constexpr int kM = kS * kT * kB;          // 32768 rows, m = u*8 + b
constexpr int BM = 128, BN = 128, BK = 64, STAGES = 3;
constexpr int kStageBytes = (BM * BK + BN * BK) * 2;     // 32 KB
constexpr int kSmemGemm = STAGES * kStageBytes;          // 96 KB
constexpr int kKIters = 2 * (kNin / BK);                 // 32 (lo pass + hi pass)
constexpr int kRing = 6;                                 // k4 ring depth (48 KB)
}  // namespace

// Scratch (device globals; no allocation allowed).
__device__ float g_snn[(size_t)kB * kS * kNin];                   //   4 MB
__device__ __align__(16) __half g_sin[(size_t)kM * kNin];         //  64 MB
__device__ __align__(16) __half g_Wt[2][(size_t)kNout * kNin];    //   4 MB
__device__ __align__(16) __half g_Wout[2][(size_t)kD * kNout];    //   2 MB
__device__ float g_cur[(size_t)kM * kNout];                       // 128 MB
__device__ __align__(16) __half g_sacch[(size_t)kS * kB * kNout]; //   2 MB
__device__ unsigned long long g_spk;

// ------------------------------- helpers ----------------------------------
__device__ __forceinline__ uint32_t smem_u32(const void* p) {
  uint32_t a;
  asm("{ .reg .u64 t; cvta.to.shared.u64 t, %1; cvt.u32.u64 %0, t; }"
      : "=r"(a) : "l"(p));
  return a;
}
__device__ __forceinline__ uint32_t swz128(uint32_t off) {
  return off ^ ((off >> 3) & 0x70);   // 16B-chunk xor within 128B rows
}
__device__ __forceinline__ void cp_async16(uint32_t dst, const void* src) {
  asm volatile("cp.async.cg.shared.global [%0], [%1], 16;"
               :: "r"(dst), "l"(src) : "memory");
}
__device__ __forceinline__ void ldsm_x4(uint32_t* r, uint32_t addr) {
  asm volatile("ldmatrix.sync.aligned.m8n8.x4.shared.b16 {%0,%1,%2,%3}, [%4];"
               : "=r"(r[0]), "=r"(r[1]), "=r"(r[2]), "=r"(r[3]) : "r"(addr));
}
__device__ __forceinline__ void mma16816(float* c, const uint32_t* a,
                                         const uint32_t* b) {
  asm volatile(
      "mma.sync.aligned.m16n8k16.row.col.f32.f16.f16.f32 "
      "{%0,%1,%2,%3}, {%4,%5,%6,%7}, {%8,%9}, {%0,%1,%2,%3};"
      : "+f"(c[0]), "+f"(c[1]), "+f"(c[2]), "+f"(c[3])
      : "r"(a[0]), "r"(a[1]), "r"(a[2]), "r"(a[3]), "r"(b[0]), "r"(b[1]));
}
__device__ __forceinline__ void split16(float w, __half& hi, __half& lo) {
  hi = __float2half_rn(w);
  lo = __float2half_rn((w - __half2float(hi)) * 2048.0f);
}

// ---------------------------------------------------------------------------
// k0: transpose + split W_conn [k][n] -> g_Wt[{hi,lo}][n][k]. Zeroes g_spk.
// ---------------------------------------------------------------------------
__global__ void k0_prep(const float* __restrict__ W) {
  __shared__ float t[32][33];
  const int tx = threadIdx.x, ty = threadIdx.y;  // (32, 8)
  const int n0 = blockIdx.x * 32, k0 = blockIdx.y * 32;
  if (blockIdx.x == 0 && blockIdx.y == 0 && tx == 0 && ty == 0) g_spk = 0ull;
#pragma unroll
  for (int i = ty; i < 32; i += 8)
    t[i][tx] = W[(size_t)(k0 + i) * kNout + n0 + tx];
  __syncthreads();
#pragma unroll
  for (int i = ty; i < 32; i += 8) {
    const int n = n0 + i, k = k0 + tx;
    __half hi, lo;
    split16(t[tx][i], hi, lo);
    const size_t off = (size_t)n * kNin + k;
    g_Wt[0][off] = hi; g_Wt[1][off] = lo;
  }
}

// k0c: transpose + split W_out [1024][512] -> g_Wout[.][d][k], k<1024.
__global__ void k0c_wout(const float* __restrict__ W) {
  __shared__ float t[32][33];
  const int tx = threadIdx.x, ty = threadIdx.y;
  const int d0 = blockIdx.x * 32, k0 = blockIdx.y * 32;
#pragma unroll
  for (int i = ty; i < 32; i += 8)
    t[i][tx] = W[(size_t)(k0 + i) * kD + d0 + tx];
  __syncthreads();
#pragma unroll
  for (int i = ty; i < 32; i += 8) {
    const int d = d0 + i, k = k0 + tx;
    __half hi, lo;
    split16(t[tx][i], hi, lo);
    const size_t off = (size_t)d * kNout + k;
    g_Wout[0][off] = hi; g_Wout[1][off] = lo;
  }
}

// ---------------------------------------------------------------------------
// k1: 64x64x16 tiled fp32 GEMM, C = relu(emb @ W_in + b_in). [1024x1024] K=512.
// (proven — input-population path must stay fp32-exact)
// ---------------------------------------------------------------------------
__global__ void k1_gemm_in(const float* __restrict__ A, const float* __restrict__ W,
                           const float* __restrict__ bias) {
  __shared__ float As[16][66];
  __shared__ float Bs[16][64];
  const int tid = threadIdx.x;
  const int bm = blockIdx.y * 64, bn = blockIdx.x * 64;
  const int tr = (tid >> 4) * 4, tc = (tid & 15) * 4;
  const int arow = tid >> 2, ak = (tid & 3) * 4;
  const int brow = tid >> 4, bcol = (tid & 15) * 4;

  float acc[4][4] = {};
  for (int kk = 0; kk < kD; kk += 16) {
    float4 av = *reinterpret_cast<const float4*>(&A[(size_t)(bm + arow) * kD + kk + ak]);
    float4 bv = *reinterpret_cast<const float4*>(&W[(size_t)(kk + brow) * kNin + bn + bcol]);
    As[ak + 0][arow] = av.x; As[ak + 1][arow] = av.y;
    As[ak + 2][arow] = av.z; As[ak + 3][arow] = av.w;
    *reinterpret_cast<float4*>(&Bs[brow][bcol]) = bv;
    __syncthreads();
#pragma unroll
    for (int k = 0; k < 16; k++) {
      float a[4], b[4];
#pragma unroll
      for (int i = 0; i < 4; i++) a[i] = As[k][tr + i];
#pragma unroll
      for (int j = 0; j < 4; j++) b[j] = Bs[k][tc + j];
#pragma unroll
      for (int i = 0; i < 4; i++)
#pragma unroll
        for (int j = 0; j < 4; j++) acc[i][j] = fmaf(a[i], b[j], acc[i][j]);
    }
    __syncthreads();
  }
#pragma unroll
  for (int i = 0; i < 4; i++)
#pragma unroll
    for (int j = 0; j < 4; j++) {
      const int n = bn + tc + j;
      g_snn[(size_t)(bm + tr + i) * kNin + n] = fmaxf(acc[i][j] + bias[n], 0.0f);
    }
}

// ---------------------------------------------------------------------------
// k2: input LIF. Thread per (b, n-pair): dual FFMA->FSETP->FSEL chains;
// x(s+1) register-prefetched. 128 CTAs x 32 threads (round-13 proven).
// ---------------------------------------------------------------------------
__global__ void k2_vin() {
  const int id = blockIdx.x * blockDim.x + threadIdx.x;  // 4096
  const int b = id >> 9;
  const int n = (id & 511) * 2;
  const float2* xsrc =
      reinterpret_cast<const float2*>(&g_snn[(size_t)(b * kS) * kNin + n]);
  const int xstride = kNin / 2;                          // float2 units per s
  float v0 = 0.0f, v1 = 0.0f;
  float total = 0.0f;
  float2 x = xsrc[0];
  for (int s = 0; s < kS; s++) {
    float2 xn = (s + 1 < kS) ? xsrc[(size_t)(s + 1) * xstride]
                             : make_float2(0.0f, 0.0f);
    const int u0 = s * kT;
#pragma unroll
    for (int t = 0; t < kT; t++) {
      const float vn0 = fmaf(kAlpha, v0, x.x);
      const float vn1 = fmaf(kAlpha, v1, x.y);
      const float vr0 = (vn0 >= kThresh) ? vn0 - kThresh : vn0;
      const float vr1 = (vn1 >= kThresh) ? vn1 - kThresh : vn1;
      const float sp0 = vn0 - vr0;
      const float sp1 = vn1 - vr1;
      total += sp0 + sp1;
      *reinterpret_cast<__half2*>(
          &g_sin[((size_t)(u0 + t) * kB + b) * kNin + n]) =
          __floats2half2_rn(sp0, sp1);
      v0 = vr0; v1 = vr1;
    }
    x = xn;
  }
  atomicAdd(&g_spk, (unsigned long long)(unsigned)total);
}

// ---------------------------------------------------------------------------
// k3: pipelined HMMA GEMM, 64x64 warp tiles. C = s_in @ (hi + 2^-11 lo)^T.
// Block 128x128, BK=64, 3-stage cp.async, 4 warps (2m x 2n). Per ks:
// 8 LDSM feed 32 HMMA (was 6:16) — halves L1 pressure per tensor op.
// k-summation order per output element unchanged -> bit-identical currents.
// ---------------------------------------------------------------------------
__global__ void __launch_bounds__(128, 2) k3_gemm() {
  extern __shared__ char smem[];
  const uint32_t sbase = smem_u32(smem);
  const int tid = threadIdx.x, wid = tid >> 5, lane = tid & 31;
  const int wm = wid >> 1, wn = wid & 1;           // 2 x 2 warp grid, 64x64 tiles
  const int m0 = blockIdx.y * BM, n0 = blockIdx.x * BN;

  auto issue_stage = [&](int kv) {
    if (kv < kKIters) {
      const int stage = kv % STAGES;
      const uint32_t as = sbase + stage * kStageBytes;
      const uint32_t bs = as + BM * BK * 2;
      const int plane = kv >> 4;
      const size_t kt = (size_t)(kv & 15) * BK;
      const char* Ag = (const char*)g_sin + ((size_t)m0 * kNin + kt) * 2;
      const char* Bg = (const char*)(plane ? g_Wt[0] : g_Wt[1]) +
                       ((size_t)n0 * kNin + kt) * 2;
#pragma unroll
      for (int i = 0; i < 8; i++) {                // A: 128 rows x 8 chunks
        const int cid = tid + i * 128;
        const int r = cid >> 3, c = cid & 7;
        cp_async16(as + swz128((uint32_t)r * 128 + c * 16),
                   Ag + (size_t)r * (kNin * 2) + c * 16);
      }
#pragma unroll
      for (int i = 0; i < 8; i++) {                // B: 128 rows x 8 chunks
        const int cid = tid + i * 128;
        const int r = cid >> 3, c = cid & 7;
        cp_async16(bs + swz128((uint32_t)r * 128 + c * 16),
                   Bg + (size_t)r * (kNin * 2) + c * 16);
      }
    }
    asm volatile("cp.async.commit_group;" ::: "memory");
  };

  issue_stage(0);
  issue_stage(1);

  float acc[4][8][4] = {};
  const int a_row = wm * 64 + (lane & 15);
  const int a_half = lane >> 4;                    // 16B half select
  const int b_row0 = wn * 64 + ((lane >> 4) * 8) + (lane & 7);
  const int b_half = (lane >> 3) & 1;

  for (int kv = 0; kv < kKIters; kv++) {
    asm volatile("cp.async.wait_group 1;" ::: "memory");
    __syncthreads();
    if (kv == kKIters / 2) {                       // lo pass done: rescale
#pragma unroll
      for (int i = 0; i < 4; i++)
#pragma unroll
        for (int j = 0; j < 8; j++)
#pragma unroll
          for (int q = 0; q < 4; q++) acc[i][j][q] *= (1.0f / 2048.0f);
    }
    const int stage = kv % STAGES;
    const uint32_t as = sbase + stage * kStageBytes;
    const uint32_t bs = as + BM * BK * 2;
#pragma unroll
    for (int ks = 0; ks < 4; ks++) {               // 4 x k16 per stage
      uint32_t a[4][4], b[8][2];
#pragma unroll
      for (int i = 0; i < 4; i++)
        ldsm_x4(a[i], as + swz128((uint32_t)(a_row + i * 16) * 128 +
                                  (ks * 2 + a_half) * 16));
#pragma unroll
      for (int jj = 0; jj < 4; jj++) {
        uint32_t r[4];
        ldsm_x4(r, bs + swz128((uint32_t)(b_row0 + jj * 16) * 128 +
                               (ks * 2 + b_half) * 16));
        b[2 * jj][0] = r[0]; b[2 * jj][1] = r[1];
        b[2 * jj + 1][0] = r[2]; b[2 * jj + 1][1] = r[3];
      }
#pragma unroll
      for (int i = 0; i < 4; i++)
#pragma unroll
        for (int j = 0; j < 8; j++) mma16816(acc[i][j], a[i], b[j]);
    }
    issue_stage(kv + 2);
  }

  // --- epilogue: stage through smem for coalesced float4 stores ---
  __syncthreads();
  float* E = reinterpret_cast<float*>(smem);       // 128 x 128 f32 (64 KB)
  const int er = lane >> 2, ec = (lane & 3) * 2;
#pragma unroll
  for (int i = 0; i < 4; i++)
#pragma unroll
    for (int j = 0; j < 8; j++) {
      float* e0 = &E[(size_t)(wm * 64 + i * 16 + er) * BN + wn * 64 + j * 8 + ec];
      e0[0] = acc[i][j][0]; e0[1] = acc[i][j][1];
      float* e1 = e0 + 8 * BN;
      e1[0] = acc[i][j][2]; e1[1] = acc[i][j][3];
    }
  __syncthreads();
#pragma unroll
  for (int q = 0; q < 32; q++) {
    const int idx = tid + q * 128;                 // 4096 float4
    const int r = idx >> 5, c4 = (idx & 31) * 4;
    *reinterpret_cast<float4*>(&g_cur[(size_t)(m0 + r) * kNout + n0 + c4]) =
        *reinterpret_cast<const float4*>(&E[(size_t)r * BN + c4]);
  }
}

// ---------------------------------------------------------------------------
// k4: output LIF via cp.async smem ring (slot = position % kRing). 64 threads
// per CTA, 1 j-column each; fp16 spike_acc stores.
// ---------------------------------------------------------------------------
__global__ void __launch_bounds__(64) k4_vout() {
  __shared__ __align__(16) float sbuf[kRing][kT][64];  // 48 KB ring
  const int tid = threadIdx.x;
  const int b = blockIdx.y;
  const int j0 = blockIdx.x * 64;
  const uint32_t sb = smem_u32(sbuf);

#pragma unroll
  for (int s = 0; s < kRing - 1; s++) {
#pragma unroll
    for (int q = 0; q < 8; q++) {
      const int c = tid + q * 64;
      const int t = c >> 4, x = c & 15;
      cp_async16(sb + (uint32_t)(((s * kT + t) * 64) + x * 4) * 4,
                 &g_cur[((size_t)(s * kT + t) * kB + b) * kNout + j0 + x * 4]);
    }
    asm volatile("cp.async.commit_group;" ::: "memory");
  }

  float v = 0.0f;
  float total = 0.0f;
  for (int s = 0; s < kS; s++) {
    asm volatile("cp.async.wait_group %0;" :: "n"(kRing - 2) : "memory");
    __syncthreads();
    const int buf = s % kRing;
    float acc = 0.0f;
#pragma unroll
    for (int t = 0; t < kT; t++) {
      const float vn = fmaf(kAlpha, v, sbuf[buf][t][tid]);
      const float vr = (vn >= kThresh) ? vn - kThresh : vn;
      acc += vn - vr;
      v = vr;
    }
    g_sacch[(size_t)(s * kB + b) * kNout + j0 + tid] = __float2half_rn(acc);
    total += acc;
    __syncthreads();
    const int sn = s + kRing - 1;
    if (sn < kS) {
      const int slot = sn % kRing;
#pragma unroll
      for (int q = 0; q < 8; q++) {
        const int c = tid + q * 64;
        const int t = c >> 4, x = c & 15;
        cp_async16(sb + (uint32_t)(((slot * kT + t) * 64) + x * 4) * 4,
                   &g_cur[((size_t)(sn * kT + t) * kB + b) * kNout + j0 + x * 4]);
      }
    }
    asm volatile("cp.async.commit_group;" ::: "memory");
  }
  atomicAdd(&g_spk, (unsigned long long)(unsigned)total);
}

// ---------------------------------------------------------------------------
// k5h: HMMA GEMM. out = spike_acc @ W_out + b_out, permuted store [b][s][d].
// M=1024 (rows s*8+b), N=512, K=1024; lo pass then hi pass (A is exact fp16).
// ---------------------------------------------------------------------------
__global__ void __launch_bounds__(256, 2) k5h_gemm(const float* __restrict__ bias,
                                                   float* __restrict__ out,
                                                   int write_rate) {
  extern __shared__ char smem[];
  const uint32_t sbase = smem_u32(smem);
  const int tid = threadIdx.x, wid = tid >> 5, lane = tid & 31;
  const int wm = wid >> 2, wn = wid & 3;
  const int m0 = blockIdx.y * BM, n0 = blockIdx.x * BN;
  constexpr int IT = 32;

  auto issue_stage = [&](int kv) {
    if (kv < IT) {
      const int stage = kv % STAGES;
      const uint32_t as = sbase + stage * kStageBytes;
      const uint32_t bs = as + BM * BK * 2;
      const size_t kt = (size_t)(kv & 15) * BK;
      const __half* Bp = (kv < 16) ? g_Wout[1] : g_Wout[0];
      const char* Ag = (const char*)(g_sacch + (size_t)m0 * kNout + kt);
      const char* Bg = (const char*)(Bp + (size_t)n0 * kNout + kt);
#pragma unroll
      for (int i = 0; i < 4; i++) {
        const int cid = tid + i * 256;
        const int r = cid >> 3, c = cid & 7;
        cp_async16(as + swz128((uint32_t)r * 128 + c * 16),
                   Ag + (size_t)r * (kNout * 2) + c * 16);
      }
#pragma unroll
      for (int i = 0; i < 4; i++) {
        const int cid = tid + i * 256;
        const int r = cid >> 3, c = cid & 7;
        cp_async16(bs + swz128((uint32_t)r * 128 + c * 16),
                   Bg + (size_t)r * (kNout * 2) + c * 16);
      }
    }
    asm volatile("cp.async.commit_group;" ::: "memory");
  };

  issue_stage(0);
  issue_stage(1);

  float acc[4][4][4] = {};
  const int a_row = wm * 64 + (lane & 15);
  const int a_half = lane >> 4;
  const int b_row0 = wn * 32 + ((lane >> 4) * 8) + (lane & 7);
  const int b_half = (lane >> 3) & 1;

  for (int kv = 0; kv < IT; kv++) {
    asm volatile("cp.async.wait_group 1;" ::: "memory");
    __syncthreads();
    if (kv == 16) {
#pragma unroll
      for (int i = 0; i < 4; i++)
#pragma unroll
        for (int j = 0; j < 4; j++)
#pragma unroll
          for (int q = 0; q < 4; q++) acc[i][j][q] *= (1.0f / 2048.0f);
    }
    const int stage = kv % STAGES;
    const uint32_t as = sbase + stage * kStageBytes;
    const uint32_t bs = as + BM * BK * 2;
#pragma unroll
    for (int ks = 0; ks < 4; ks++) {
      uint32_t a[4][4], b[4][2];
#pragma unroll
      for (int i = 0; i < 4; i++)
        ldsm_x4(a[i], as + swz128((uint32_t)(a_row + i * 16) * 128 +
                                  (ks * 2 + a_half) * 16));
#pragma unroll
      for (int jj = 0; jj < 2; jj++) {
        uint32_t r[4];
        ldsm_x4(r, bs + swz128((uint32_t)(b_row0 + jj * 16) * 128 +
                               (ks * 2 + b_half) * 16));
        b[2 * jj][0] = r[0]; b[2 * jj][1] = r[1];
        b[2 * jj + 1][0] = r[2]; b[2 * jj + 1][1] = r[3];
      }
#pragma unroll
      for (int i = 0; i < 4; i++)
#pragma unroll
        for (int j = 0; j < 4; j++) mma16816(acc[i][j], a[i], b[j]);
    }
    issue_stage(kv + 2);
  }

  __syncthreads();
  float* E = reinterpret_cast<float*>(smem);
  const int er = lane >> 2, ec = (lane & 3) * 2;
#pragma unroll
  for (int i = 0; i < 4; i++)
#pragma unroll
    for (int j = 0; j < 4; j++) {
      float* e0 = &E[(size_t)(wm * 64 + i * 16 + er) * BN + wn * 32 + j * 8 + ec];
      e0[0] = acc[i][j][0]; e0[1] = acc[i][j][1];
      float* e1 = e0 + 8 * BN;
      e1[0] = acc[i][j][2]; e1[1] = acc[i][j][3];
    }
  __syncthreads();
  if (write_rate && blockIdx.x == 0 && blockIdx.y == 0 && tid == 0) {
    out[(size_t)kB * kS * kD] =
        (float)((double)g_spk / (double)((size_t)kB * kS * (kNin + kNout) * kT));
  }
#pragma unroll
  for (int q = 0; q < 16; q++) {
    const int idx = tid + q * 256;
    const int r = idx >> 5, c4 = (idx & 31) * 4;
    const int m = m0 + r;
    const int s = m >> 3, b = m & 7;       // rows are m = s*B + b
    float4 v = *reinterpret_cast<const float4*>(&E[(size_t)r * BN + c4]);
    const float4 bb = *reinterpret_cast<const float4*>(&bias[n0 + c4]);
    v.x += bb.x; v.y += bb.y; v.z += bb.z; v.w += bb.w;
    *reinterpret_cast<float4*>(&out[((size_t)(b * kS + s)) * kD + n0 + c4]) = v;
  }
}

// ---------------------------------------------------------------------------
extern "C" void kernel_launch(void* const* d_in, const int* in_sizes, int n_in,
                              void* d_out, int out_size) {
  const float* emb    = (const float*)d_in[0];
  const float* W_in   = (const float*)d_in[1];
  const float* b_in   = (const float*)d_in[2];
  const float* W_conn = (const float*)d_in[3];
  const float* W_out  = (const float*)d_in[4];
  const float* b_out  = (const float*)d_in[5];
  float* out = (float*)d_out;
  const int write_rate = (out_size > kB * kS * kD) ? 1 : 0;

  cudaFuncSetAttribute(k3_gemm, cudaFuncAttributeMaxDynamicSharedMemorySize, kSmemGemm);
  cudaFuncSetAttribute(k5h_gemm, cudaFuncAttributeMaxDynamicSharedMemorySize, kSmemGemm);

  k0_prep<<<dim3(kNout / 32, kNin / 32), dim3(32, 8)>>>(W_conn);
  k0c_wout<<<dim3(kD / 32, kNout / 32), dim3(32, 8)>>>(W_out);
  k1_gemm_in<<<dim3(kNin / 64, (kB * kS) / 64), 256>>>(emb, W_in, b_in);
  k2_vin<<<128, 32>>>();
  k3_gemm<<<dim3(kNout / BN, kM / BM), 128, kSmemGemm>>>();
  k4_vout<<<dim3(kNout / 64, kB), 64>>>();
  k5h_gemm<<<dim3(kD / BN, (kS * kB) / BM), 256, kSmemGemm>>>(b_out, out, write_rate);
}